// round 4
// baseline (speedup 1.0000x reference)
#include <cuda_runtime.h>

namespace {
constexpr int Hn  = 256;   // heads
constexpr int NH  = 64;    // complex modes per head
constexpr int Lk  = 2048;  // kernel length
constexpr int LH  = 1025;  // rfft bins
constexpr int LHP = 1026;  // padded stride (float2) so per-head base is 16B-aligned
constexpr float TWO_PI = 6.28318530717958647692f;
}

// Inter-kernel scratch: spectrum k_f (2.1 MB, L2-resident)
__device__ float2 g_kf[Hn * LHP];

// ---------------- packed f32x2 helpers (FFMA2 path, PTX-only) ---------------
typedef unsigned long long u64;

__device__ __forceinline__ u64 pk2(float lo, float hi) {
    u64 r;
    asm("mov.b64 %0, {%1, %2};" : "=l"(r)
        : "r"(__float_as_uint(lo)), "r"(__float_as_uint(hi)));
    return r;
}
__device__ __forceinline__ void upk2(u64 v, float& lo, float& hi) {
    unsigned a, b;
    asm("mov.b64 {%0, %1}, %2;" : "=r"(a), "=r"(b) : "l"(v));
    lo = __uint_as_float(a); hi = __uint_as_float(b);
}
__device__ __forceinline__ u64 add2_(u64 a, u64 b) {
    u64 d; asm("add.rn.f32x2 %0, %1, %2;" : "=l"(d) : "l"(a), "l"(b)); return d;
}
__device__ __forceinline__ u64 mul2_(u64 a, u64 b) {
    u64 d; asm("mul.rn.f32x2 %0, %1, %2;" : "=l"(d) : "l"(a), "l"(b)); return d;
}
__device__ __forceinline__ u64 fma2_(u64 a, u64 b, u64 c) {
    u64 d; asm("fma.rn.f32x2 %0, %1, %2, %3;" : "=l"(d) : "l"(a), "l"(b), "l"(c)); return d;
}
__device__ __forceinline__ u64 rcp2_(u64 v) {   // per-lane MUFU.RCP (== __fdividef(1,x))
    float lo, hi; upk2(v, lo, hi);
    float rl, rh;
    asm("rcp.approx.f32 %0, %1;" : "=f"(rl) : "f"(lo));
    asm("rcp.approx.f32 %0, %1;" : "=f"(rh) : "f"(hi));
    return pk2(rl, rh);
}

// Per-mode constants, pre-duplicated (and pre-negated where needed) for f32x2.
struct __align__(16) CPack {
    ulonglong2 a;  // { {-wx,-wx}, {-wy,-wy} }
    ulonglong2 b;  // { { wy, wy}, {v00r,v00r} }
    ulonglong2 c;  // { {-v00i,-v00i}, {v01r,v01r} }
    ulonglong2 d;  // { {-v01i,-v01i}, {v10r,v10r} }
    ulonglong2 e;  // { {-v10i,-v10i}, {v11r,v11r} }
};

// ---------------------------------------------------------------------------
// Compute k_f for two bins (j0 packed in lane-lo, j1 in lane-hi).
// ---------------------------------------------------------------------------
__device__ __forceinline__ float4 compute_pair(
    float j0, float j1, const CPack* __restrict__ sh)
{
    // ACCURATE sincosf: at j=1024 the angle is ~-pi, |sin| ~ 1.4e-7;
    // __sincosf abs error can hit exact 0 -> inf -> NaN.
    float zrS[2], ziS[2], drS[2], diS[2], dnS[2];
    const float jj[2] = { j0, j1 };
#pragma unroll
    for (int k = 0; k < 2; k++) {
        float sw, cw;
        sincosf(-TWO_PI / (float)Lk * jj[k], &sw, &cw);
        const float dr = 1.0f + cw, di = sw;                  // 1 + omega
        const float dn = __fdividef(1.0f, dr * dr + di * di);
        const float nr = 2.0f * (1.0f - cw), ni = -2.0f * sw; // 2(1-omega)
        zrS[k] = (nr * dr + ni * di) * dn;                    // z
        ziS[k] = (ni * dr - nr * di) * dn;
        drS[k] = dr; diS[k] = di; dnS[k] = dn;
    }
    const u64 zr2 = pk2(zrS[0], zrS[1]);
    const u64 zi2 = pk2(ziS[0], ziS[1]);
    const u64 NEG1 = 0xBF800000BF800000ull;  // {-1.f, -1.f}

    u64 a00r = 0, m00i = 0, a01r = 0, m01i = 0;
    u64 a10r = 0, m10i = 0, a11r = 0, m11i = 0;

#pragma unroll 8
    for (int n = 0; n < NH; n++) {
        const CPack cp = sh[n];
        const u64 er   = add2_(zr2, cp.a.x);            // zr - wx
        const u64 ei1  = add2_(zi2, cp.a.y);            // zi - wy
        const u64 ei2  = add2_(zi2, cp.b.x);            // zi + wy
        const u64 er2p = mul2_(er, er);
        const u64 rc1  = rcp2_(fma2_(ei1, ei1, er2p));
        const u64 rc2  = rcp2_(fma2_(ei2, ei2, er2p));
        const u64 t1   = mul2_(ei1, rc1);
        const u64 t2   = mul2_(ei2, rc2);
        const u64 sA   = mul2_(er, add2_(rc1, rc2));
        const u64 sD   = mul2_(er, fma2_(rc2, NEG1, rc1));   // er*(rc1-rc2)
        const u64 sB   = fma2_(t1, NEG1, t2);                // t2 - t1
        const u64 sCn  = add2_(t1, t2);
        // real accums: += v_r*sA - v_i*sB ; negated-imag accums: += v_r*sCn - v_i*sD
        a00r = fma2_(cp.b.y, sA,  fma2_(cp.c.x, sB, a00r));
        m00i = fma2_(cp.b.y, sCn, fma2_(cp.c.x, sD, m00i));
        a01r = fma2_(cp.c.y, sA,  fma2_(cp.d.x, sB, a01r));
        m01i = fma2_(cp.c.y, sCn, fma2_(cp.d.x, sD, m01i));
        a10r = fma2_(cp.d.y, sA,  fma2_(cp.e.x, sB, a10r));
        m10i = fma2_(cp.d.y, sCn, fma2_(cp.e.x, sD, m10i));
        a11r = fma2_(cp.e.y, sA,  a11r);                     // v11 real
        m11i = fma2_(cp.e.y, sCn, m11i);
    }

    float r00[2], i00[2], r01[2], i01[2], r10[2], i10[2], r11[2], i11[2];
    upk2(a00r, r00[0], r00[1]); upk2(m00i, i00[0], i00[1]);
    upk2(a01r, r01[0], r01[1]); upk2(m01i, i01[0], i01[1]);
    upk2(a10r, r10[0], r10[1]); upk2(m10i, i10[0], i10[1]);
    upk2(a11r, r11[0], r11[1]); upk2(m11i, i11[0], i11[1]);

    float kf[4];
#pragma unroll
    for (int k = 0; k < 2; k++) {
        const float a00i = -i00[k], a01i = -i01[k];
        const float a10i = -i10[k], a11i = -i11[k];
        // k_f = (r00 - r01*r10/(1+r11)) * 2/(1+omega)
        const float qr = 1.0f + r11[k], qi = a11i;
        const float qn = __fdividef(1.0f, qr * qr + qi * qi);
        const float tr = r01[k] * r10[k] - a01i * a10i;
        const float ti = r01[k] * a10i + a01i * r10[k];
        const float kr = r00[k] - (tr * qr + ti * qi) * qn;
        const float ki = a00i   - (ti * qr - tr * qi) * qn;
        const float fr =  2.0f * drS[k] * dnS[k];
        const float fi = -2.0f * diS[k] * dnS[k];
        kf[2 * k]     = kr * fr - ki * fi;
        kf[2 * k + 1] = kr * fi + ki * fr;
    }
    return make_float4(kf[0], kf[1], kf[2], kf[3]);
}

// ---------------------------------------------------------------------------
// K1: spectrum. grid (4, 256) x 128 thr; thread T in [0,512) -> bins (2T, 2T+1).
// Nyquist bin 1024 piggy-backs on (bx=0, tid=0).
// ---------------------------------------------------------------------------
__global__ void __launch_bounds__(128) k_spectrum(
    const float* __restrict__ w_ri,
    const float* __restrict__ P_ri,
    const float* __restrict__ B_ri,
    const float* __restrict__ C_ri,
    const float* __restrict__ log_dt)
{
    __shared__ CPack sh[NH];

    const int h = blockIdx.y;
    const int tid = threadIdx.x;

    if (tid < NH) {
        const float dt = expf(log_dt[h]);
        const int base = (h * NH + tid) * 2;
        const float wx = w_ri[base] * dt, wy = w_ri[base + 1] * dt;
        const float pr = P_ri[base], pi = P_ri[base + 1];
        const float br = B_ri[base], bi = B_ri[base + 1];
        const float cr = C_ri[base], ci = C_ri[base + 1];
        // dt folded into numerators
        const float v00r = dt * (br * cr - bi * ci), v00i = dt * (br * ci + bi * cr);
        const float v01r = dt * (br * pr + bi * pi), v01i = dt * (bi * pr - br * pi);
        const float v10r = dt * (pr * cr - pi * ci), v10i = dt * (pr * ci + pi * cr);
        const float v11r = dt * (pr * pr + pi * pi);
        CPack cp;
        cp.a.x = pk2(-wx, -wx);     cp.a.y = pk2(-wy, -wy);
        cp.b.x = pk2( wy,  wy);     cp.b.y = pk2(v00r, v00r);
        cp.c.x = pk2(-v00i, -v00i); cp.c.y = pk2(v01r, v01r);
        cp.d.x = pk2(-v01i, -v01i); cp.d.y = pk2(v10r, v10r);
        cp.e.x = pk2(-v10i, -v10i); cp.e.y = pk2(v11r, v11r);
        sh[tid] = cp;
    }
    __syncthreads();

    float2* kf = g_kf + h * LHP;
    const int T = blockIdx.x * 128 + tid;     // [0, 512)
    const float j0 = (float)(2 * T);
    const float4 r = compute_pair(j0, j0 + 1.0f, sh);
    reinterpret_cast<float4*>(kf)[T] = r;     // bins 2T, 2T+1 (16B-aligned)

    if (blockIdx.x == 0 && tid == 0) {
        const float4 ny = compute_pair(1024.0f, 1024.0f, sh);
        kf[1024] = make_float2(ny.x, ny.y);
    }
}

// ---------------------------------------------------------------------------
// K2: per-head inverse complex DFT. Stage 0 (radix-2) fused with Hermitian
// load, then 5 radix-4 Stockham stages (s = 1,3,5,7,9).
// Y[t] = sum_j X[j] e^{+2 pi i j t / N}
// ---------------------------------------------------------------------------
__global__ void __launch_bounds__(256) k_ifft(float* __restrict__ out)
{
    __shared__ float2 bufA[Lk];   // 16 KB
    __shared__ float2 bufB[Lk];   // 16 KB

    const int h = blockIdx.x;
    const int tid = threadIdx.x;
    const float2* __restrict__ kf = g_kf + h * LHP;

    // stage 0: a = X[u], b = X[u+1024] via Hermitian mirror; outputs (2u, 2u+1)
    for (int u = tid; u < Lk / 2; u += 256) {
        const float2 a = kf[u];
        float2 b;
        if (u == 0) b = kf[1024];
        else { const float2 t = kf[1024 - u]; b = make_float2(t.x, -t.y); }
        float s, c;
        __sincosf(TWO_PI / (float)Lk * (float)u, &s, &c);
        const float ax = a.x - b.x, ay = a.y - b.y;
        reinterpret_cast<float4*>(bufA)[u] =
            make_float4(a.x + b.x, a.y + b.y, ax * c - ay * s, ax * s + ay * c);
    }
    __syncthreads();

    float2* cur = bufA;
    float2* nxt = bufB;
#pragma unroll
    for (int s = 1; s <= 9; s += 2) {
        const float step = TWO_PI * (float)(1 << s) / (float)Lk;
#pragma unroll 2
        for (int g = tid; g < Lk / 4; g += 256) {
            const int p  = g >> s;
            const int lo = g & ((1 << s) - 1);
            const int u1 = (p << s) | lo;
            const int u2 = u1 + Lk / 4;
            const float2 x0 = cur[u1], x2 = cur[u1 + Lk / 2];
            const float2 x1 = cur[u2], x3 = cur[u2 + Lk / 2];
            float s1, c1;
            __sincosf(step * (float)p, &s1, &c1);   // args in [0, pi/2): safe
            // radix-2 stage s:
            const float2 A0 = make_float2(x0.x + x2.x, x0.y + x2.y);
            const float dx = x0.x - x2.x, dy = x0.y - x2.y;
            const float2 A1 = make_float2(dx * c1 - dy * s1, dx * s1 + dy * c1);
            const float2 B0 = make_float2(x1.x + x3.x, x1.y + x3.y);
            const float ex = x1.x - x3.x, ey = x1.y - x3.y;
            const float tr = ex * c1 - ey * s1, ti = ex * s1 + ey * c1;
            const float2 B1 = make_float2(-ti, tr);        // i * (D1 * tw1)
            // radix-2 stage s+1 with tw3 = tw1^2:
            const float c3 = c1 * c1 - s1 * s1, s3 = 2.0f * c1 * s1;
            const int O = (p << (s + 2)) | lo;
            const int q = 1 << s;
            nxt[O] = make_float2(A0.x + B0.x, A0.y + B0.y);
            const float fx = A0.x - B0.x, fy = A0.y - B0.y;
            nxt[O + 2 * q] = make_float2(fx * c3 - fy * s3, fx * s3 + fy * c3);
            nxt[O + q] = make_float2(A1.x + B1.x, A1.y + B1.y);
            const float gx = A1.x - B1.x, gy = A1.y - B1.y;
            nxt[O + 3 * q] = make_float2(gx * c3 - gy * s3, gx * s3 + gy * c3);
        }
        __syncthreads();
        float2* t = cur; cur = nxt; nxt = t;
    }
    // 5 swaps: final data is in the buffer cur now points at.

    const float inv = 1.0f / (float)Lk;
    float* o = out + h * Lk;
#pragma unroll 4
    for (int t = tid; t < Lk; t += 256)
        o[t] = cur[t].x * inv;
}

extern "C" void kernel_launch(void* const* d_in, const int* in_sizes, int n_in,
                              void* d_out, int out_size) {
    // metadata order: w_ri, P_ri, B_ri, C_ri, log_dt, L (L fixed at 2048)
    k_spectrum<<<dim3(4, Hn), 128>>>(
        (const float*)d_in[0],
        (const float*)d_in[1],
        (const float*)d_in[2],
        (const float*)d_in[3],
        (const float*)d_in[4]);
    k_ifft<<<Hn, 256>>>((float*)d_out);
}

// round 5
// speedup vs baseline: 1.4035x; 1.4035x over previous
#include <cuda_runtime.h>
#include <math.h>

namespace {
constexpr int Hn  = 256;   // heads
constexpr int NH  = 64;    // complex modes per head
constexpr int Lk  = 2048;  // kernel length
constexpr int LHP = 1026;  // padded float2 stride per head
constexpr float TWO_PI = 6.28318530717958647692f;
constexpr float PI_F   = 3.14159265358979323846f;
}

// Inter-kernel scratch: spectrum k_f (2.1 MB, L2-resident)
__device__ float2 g_kf[Hn * LHP];

__device__ __forceinline__ float frcp(float x) {
    float r; asm("rcp.approx.f32 %0, %1;" : "=f"(r) : "f"(x)); return r;
}

// ---------------------------------------------------------------------------
// K1: spectrum.  z = i*y with y = 2*tan(pi*j/L)  (purely imaginary!).
// Conjugate pole pair combined over a real-coefficient denominator:
//   v/(z-w) + conj(v)/(z-conj(w)) = (i*alpha*y - beta) / D
//   D = (|w|^2 - y^2) - i*(2*Re(w)*y),  alpha = 2*Re(v), beta = 2*Re(v*conj(w))
// With q = 1/|D|^2, P1 = u*q, P2 = s*q  (u = |w|^2-y^2, s = 2Re(w)*y):
//   Re r_k = -(Sb_k + y*Sc_k),  Im r_k = y*Sa_k - Sd_k
//   Sa=SUM alpha*P1, Sb=SUM beta*P1, Sc=SUM alpha*P2, Sd=SUM beta*P2
// Final factor: 2/(1+omega) = 1 + i*y/2.   Nyquist: k_f = SUM Re(dt*B*C), real.
// Each thread computes 2 bins (j = T and T+512) sharing the per-mode LDS.
// ---------------------------------------------------------------------------
__global__ void __launch_bounds__(256) k_spectrum(
    const float* __restrict__ w_ri,
    const float* __restrict__ P_ri,
    const float* __restrict__ B_ri,
    const float* __restrict__ C_ri,
    const float* __restrict__ log_dt)
{
    __shared__ float4 shA[NH];  // {m2, cs, a00, b00}
    __shared__ float4 shB[NH];  // {a01, b01, a10, b10}
    __shared__ float2 shC[NH];  // {a11, b11}

    const int h = blockIdx.y;
    const int tid = threadIdx.x;

    if (tid < NH) {
        const float dt = expf(log_dt[h]);
        const int base = (h * NH + tid) * 2;
        const float wx = w_ri[base] * dt, wy = w_ri[base + 1] * dt;
        const float pr = P_ri[base], pi = P_ri[base + 1];
        const float br = B_ri[base], bi = B_ri[base + 1];
        const float cr = C_ri[base], ci = C_ri[base + 1];
        // numerators with dt folded in
        const float v00r = dt * (br * cr - bi * ci), v00i = dt * (br * ci + bi * cr);
        const float v01r = dt * (br * pr + bi * pi), v01i = dt * (bi * pr - br * pi);
        const float v10r = dt * (pr * cr - pi * ci), v10i = dt * (pr * ci + pi * cr);
        const float v11r = dt * (pr * pr + pi * pi);               // v11 imag = 0
        shA[tid] = make_float4(wx * wx + wy * wy,                  // m2 = |w|^2
                               2.0f * wx,                          // cs = 2 Re(w)
                               2.0f * v00r,                        // a00
                               2.0f * (v00r * wx + v00i * wy));    // b00
        shB[tid] = make_float4(2.0f * v01r, 2.0f * (v01r * wx + v01i * wy),
                               2.0f * v10r, 2.0f * (v10r * wx + v10i * wy));
        shC[tid] = make_float2(2.0f * v11r, 2.0f * v11r * wx);
    }
    __syncthreads();

    float2* kf = g_kf + h * LHP;
    const int T = blockIdx.x * 256 + tid;     // [0, 512): bins T and T+512

    const float c = PI_F / (float)Lk;
    float y[2], y2[2];
    y[0] = 2.0f * tanf(c * (float)T);
    y[1] = 2.0f * tanf(c * (float)(T + 512));
    y2[0] = y[0] * y[0];
    y2[1] = y[1] * y[1];

    // 16 accumulators per bin
    float Sa0[2]={0,0}, Sb0[2]={0,0}, Sc0[2]={0,0}, Sd0[2]={0,0};
    float Sa1[2]={0,0}, Sb1[2]={0,0}, Sc1[2]={0,0}, Sd1[2]={0,0};
    float Sa2[2]={0,0}, Sb2[2]={0,0}, Sc2[2]={0,0}, Sd2[2]={0,0};
    float Sa3[2]={0,0}, Sb3[2]={0,0}, Sc3[2]={0,0}, Sd3[2]={0,0};

#pragma unroll 4
    for (int n = 0; n < NH; n++) {
        const float4 A  = shA[n];
        const float4 Bv = shB[n];
        const float2 Cv = shC[n];
#pragma unroll
        for (int b = 0; b < 2; b++) {
            const float u = A.x - y2[b];                 // |w|^2 - y^2
            const float s = A.y * y[b];                  // 2 Re(w) * y
            const float q = frcp(fmaf(u, u, s * s));     // 1/|D|^2
            const float P1 = u * q;
            const float P2 = s * q;
            Sa0[b] = fmaf(A.z,  P1, Sa0[b]);  Sb0[b] = fmaf(A.w,  P1, Sb0[b]);
            Sc0[b] = fmaf(A.z,  P2, Sc0[b]);  Sd0[b] = fmaf(A.w,  P2, Sd0[b]);
            Sa1[b] = fmaf(Bv.x, P1, Sa1[b]);  Sb1[b] = fmaf(Bv.y, P1, Sb1[b]);
            Sc1[b] = fmaf(Bv.x, P2, Sc1[b]);  Sd1[b] = fmaf(Bv.y, P2, Sd1[b]);
            Sa2[b] = fmaf(Bv.z, P1, Sa2[b]);  Sb2[b] = fmaf(Bv.w, P1, Sb2[b]);
            Sc2[b] = fmaf(Bv.z, P2, Sc2[b]);  Sd2[b] = fmaf(Bv.w, P2, Sd2[b]);
            Sa3[b] = fmaf(Cv.x, P1, Sa3[b]);  Sb3[b] = fmaf(Cv.y, P1, Sb3[b]);
            Sc3[b] = fmaf(Cv.x, P2, Sc3[b]);  Sd3[b] = fmaf(Cv.y, P2, Sd3[b]);
        }
    }

#pragma unroll
    for (int b = 0; b < 2; b++) {
        const float r00r = -fmaf(y[b], Sc0[b], Sb0[b]);
        const float r00i =  fmaf(y[b], Sa0[b], -Sd0[b]);
        const float r01r = -fmaf(y[b], Sc1[b], Sb1[b]);
        const float r01i =  fmaf(y[b], Sa1[b], -Sd1[b]);
        const float r10r = -fmaf(y[b], Sc2[b], Sb2[b]);
        const float r10i =  fmaf(y[b], Sa2[b], -Sd2[b]);
        const float r11r = -fmaf(y[b], Sc3[b], Sb3[b]);
        const float r11i =  fmaf(y[b], Sa3[b], -Sd3[b]);
        // k = r00 - r01*r10/(1+r11)
        const float qr = 1.0f + r11r, qi = r11i;
        const float qn = frcp(fmaf(qr, qr, qi * qi));
        const float tr = r01r * r10r - r01i * r10i;
        const float ti = r01r * r10i + r01i * r10r;
        const float kr = r00r - (tr * qr + ti * qi) * qn;
        const float ki = r00i - (ti * qr - tr * qi) * qn;
        // k_f = k * (1 + i*y/2)
        const float hh = 0.5f * y[b];
        kf[T + 512 * b] = make_float2(fmaf(-ki, hh, kr), fmaf(kr, hh, ki));
    }

    // Nyquist bin: analytic limit  k_f(1024) = SUM Re(dt*B*C) = SUM a00/2, real.
    if (blockIdx.x == 0 && tid == 0) {
        float acc = 0.0f;
        for (int n = 0; n < NH; n++) acc += shA[n].z;
        kf[1024] = make_float2(0.5f * acc, 0.0f);
    }
}

// ---------------------------------------------------------------------------
// K2: per-head inverse complex DFT. Stage 0 (radix-2) fused with Hermitian
// load, then 5 radix-4 Stockham stages (s = 1,3,5,7,9). 512 threads.
// Y[t] = sum_j X[j] e^{+2 pi i j t / N}
// ---------------------------------------------------------------------------
__global__ void __launch_bounds__(512) k_ifft(float* __restrict__ out)
{
    __shared__ float2 bufA[Lk];   // 16 KB
    __shared__ float2 bufB[Lk];   // 16 KB

    const int h = blockIdx.x;
    const int tid = threadIdx.x;
    const float2* __restrict__ kf = g_kf + h * LHP;

    // stage 0: a = X[u], b = X[u+1024] via Hermitian mirror; outputs (2u, 2u+1)
#pragma unroll
    for (int u = tid; u < Lk / 2; u += 512) {
        const float2 a = kf[u];
        float2 b;
        if (u == 0) b = kf[1024];
        else { const float2 t = kf[1024 - u]; b = make_float2(t.x, -t.y); }
        float s, cc;
        __sincosf(TWO_PI / (float)Lk * (float)u, &s, &cc);
        const float ax = a.x - b.x, ay = a.y - b.y;
        reinterpret_cast<float4*>(bufA)[u] =
            make_float4(a.x + b.x, a.y + b.y, ax * cc - ay * s, ax * s + ay * cc);
    }
    __syncthreads();

    float2* cur = bufA;
    float2* nxt = bufB;
#pragma unroll
    for (int s = 1; s <= 9; s += 2) {
        const float step = TWO_PI * (float)(1 << s) / (float)Lk;
        {
            const int g = tid;                     // Lk/4 = 512 groups, 1/thread
            const int p  = g >> s;
            const int lo = g & ((1 << s) - 1);
            const int u1 = (p << s) | lo;
            const int u2 = u1 + Lk / 4;
            const float2 x0 = cur[u1], x2 = cur[u1 + Lk / 2];
            const float2 x1 = cur[u2], x3 = cur[u2 + Lk / 2];
            float s1, c1;
            __sincosf(step * (float)p, &s1, &c1);  // args in [0, pi/2): safe
            const float2 A0 = make_float2(x0.x + x2.x, x0.y + x2.y);
            const float dx = x0.x - x2.x, dy = x0.y - x2.y;
            const float2 A1 = make_float2(dx * c1 - dy * s1, dx * s1 + dy * c1);
            const float2 B0 = make_float2(x1.x + x3.x, x1.y + x3.y);
            const float ex = x1.x - x3.x, ey = x1.y - x3.y;
            const float tr = ex * c1 - ey * s1, ti = ex * s1 + ey * c1;
            const float2 B1 = make_float2(-ti, tr);          // i * (D1 * tw1)
            const float c3 = c1 * c1 - s1 * s1, s3 = 2.0f * c1 * s1;  // tw1^2
            const int O = (p << (s + 2)) | lo;
            const int q = 1 << s;
            nxt[O] = make_float2(A0.x + B0.x, A0.y + B0.y);
            const float fx = A0.x - B0.x, fy = A0.y - B0.y;
            nxt[O + 2 * q] = make_float2(fx * c3 - fy * s3, fx * s3 + fy * c3);
            nxt[O + q] = make_float2(A1.x + B1.x, A1.y + B1.y);
            const float gx = A1.x - B1.x, gy = A1.y - B1.y;
            nxt[O + 3 * q] = make_float2(gx * c3 - gy * s3, gx * s3 + gy * c3);
        }
        __syncthreads();
        float2* t = cur; cur = nxt; nxt = t;
    }

    const float inv = 1.0f / (float)Lk;
    float* o = out + h * Lk;
#pragma unroll
    for (int t = tid; t < Lk; t += 512)
        o[t] = cur[t].x * inv;
}

extern "C" void kernel_launch(void* const* d_in, const int* in_sizes, int n_in,
                              void* d_out, int out_size) {
    // metadata order: w_ri, P_ri, B_ri, C_ri, log_dt, L (L fixed at 2048)
    k_spectrum<<<dim3(2, Hn), 256>>>(
        (const float*)d_in[0],
        (const float*)d_in[1],
        (const float*)d_in[2],
        (const float*)d_in[3],
        (const float*)d_in[4]);
    k_ifft<<<Hn, 512>>>((float*)d_out);
}

// round 7
// speedup vs baseline: 1.4994x; 1.0684x over previous
#include <cuda_runtime.h>
#include <cuda_bf16.h>
#include <math.h>
#include <cstdint>

namespace {
constexpr int Hn  = 256;   // heads
constexpr int NH  = 64;    // complex modes per head
constexpr int Lk  = 2048;  // kernel length
constexpr int LHP = 1026;  // padded float2 stride per head
constexpr float TWO_PI = 6.28318530717958647692f;
constexpr float PI_F   = 3.14159265358979323846f;
}

// Inter-kernel scratch: spectrum k_f (2.1 MB, L2-resident)
__device__ float2 g_kf[Hn * LHP];

__device__ __forceinline__ float frcp(float x) {
    float r; asm("rcp.approx.f32 %0, %1;" : "=f"(r) : "f"(x)); return r;
}
// {hi16(a) | hi16(b)<<16}  (bf16-truncate both, a -> low half)
__device__ __forceinline__ uint32_t pack_hi(float a, float b) {
    uint32_t r;
    asm("prmt.b32 %0, %1, %2, 0x7632;" : "=r"(r)
        : "r"(__float_as_uint(a)), "r"(__float_as_uint(b)));
    return r;
}
__device__ __forceinline__ float trunc_bf(float x) {
    return __uint_as_float(__float_as_uint(x) & 0xFFFF0000u);
}
// round-to-nearest bf16x2 pack, a -> low half
__device__ __forceinline__ uint32_t pack_rn(float a, float b) {
    uint32_t r;
    asm("cvt.rn.satfinite.bf16x2.f32 %0, %1, %2;" : "=r"(r) : "f"(b), "f"(a));
    return r;
}
// D[16x8] += A[16x16,row] * B[16x8,col]  (bf16 in, f32 acc)
__device__ __forceinline__ void mma_bf16(float* d, const uint32_t* a,
                                         uint32_t b0, uint32_t b1) {
    asm volatile(
        "mma.sync.aligned.m16n8k16.row.col.f32.bf16.bf16.f32 "
        "{%0,%1,%2,%3}, {%4,%5,%6,%7}, {%8,%9}, {%0,%1,%2,%3};"
        : "+f"(d[0]), "+f"(d[1]), "+f"(d[2]), "+f"(d[3])
        : "r"(a[0]), "r"(a[1]), "r"(a[2]), "r"(a[3]), "r"(b0), "r"(b1));
}

// ---------------------------------------------------------------------------
// K1: spectrum via bf16-split warp MMA.
//   z = i*y, y = 2*tan(pi*j/L); per mode: u = m2 - y^2, d = u^2 + csq*y^2,
//   q = 1/d, P1 = u*q, P2' = cs*q   (m2=|w|^2, cs=2Re(w), csq=cs^2).
//   D1[bin,r] = sum_n P1*W[n,r], D2[bin,r] = sum_n P2'*W[n,r],
//   W rows(n)=mode, cols(r)=0..7: {a0,b0,a1,b1,a2,b2,a3,b3},
//   a_k = 2Re(v_k), b_k = 2Re(v_k*conj(w)).
//   Re r_k = -(D1[2k+1] + y^2*D2[2k]),  Im r_k = y*(D1[2k] - D2[2k+1])
//   k_f = (r0 - r1*r2/(1+r3)) * (1 + i*y/2).  Nyquist analytic (real).
// grid (16, 256) x 128 thr; warp = 16-bin tile, block = 64 bins of head h.
// ---------------------------------------------------------------------------
__global__ void __launch_bounds__(128) k_spectrum(
    const float* __restrict__ w_ri,
    const float* __restrict__ P_ri,
    const float* __restrict__ B_ri,
    const float* __restrict__ C_ri,
    const float* __restrict__ log_dt)
{
    __shared__ float4 sC[NH];        // {m2, cs, csq, 0}
    __shared__ float  sWf[NH * 8];   // W[mode][r], fp32
    __shared__ float  sEx[4][16][16];// per-warp transpose for epilogue

    const int h    = blockIdx.y;
    const int tid  = threadIdx.x;
    const int wid  = tid >> 5;
    const int lane = tid & 31;
    const int g    = lane >> 2;      // fragment group row / B col
    const int tig  = lane & 3;

    // ---- per-head constants + W ----
    if (tid < NH) {
        const int m = tid;
        const float dt = expf(log_dt[h]);
        const int base = (h * NH + m) * 2;
        const float wx = w_ri[base] * dt, wy = w_ri[base + 1] * dt;
        const float pr = P_ri[base], pi = P_ri[base + 1];
        const float br = B_ri[base], bi = B_ri[base + 1];
        const float cr = C_ri[base], ci = C_ri[base + 1];
        const float v00r = dt * (br * cr - bi * ci), v00i = dt * (br * ci + bi * cr);
        const float v01r = dt * (br * pr + bi * pi), v01i = dt * (bi * pr - br * pi);
        const float v10r = dt * (pr * cr - pi * ci), v10i = dt * (pr * ci + pi * cr);
        const float v11r = dt * (pr * pr + pi * pi);
        const float cs = 2.0f * wx;
        sC[m] = make_float4(wx * wx + wy * wy, cs, cs * cs, 0.0f);
        sWf[m * 8 + 0] = 2.0f * v00r;
        sWf[m * 8 + 1] = 2.0f * (v00r * wx + v00i * wy);
        sWf[m * 8 + 2] = 2.0f * v01r;
        sWf[m * 8 + 3] = 2.0f * (v01r * wx + v01i * wy);
        sWf[m * 8 + 4] = 2.0f * v10r;
        sWf[m * 8 + 5] = 2.0f * (v10r * wx + v10i * wy);
        sWf[m * 8 + 6] = 2.0f * v11r;
        sWf[m * 8 + 7] = 2.0f * v11r * wx;
    }
    __syncthreads();

    // ---- B fragments (W hi/lo), col r = g, k rows = modes ----
    uint32_t bhi0[4], bhi1[4], blo0[4], blo1[4];
#pragma unroll
    for (int kt = 0; kt < 4; kt++) {
        const int m0 = 16 * kt + 2 * tig;
        const float w0 = sWf[m0 * 8 + g],       w1 = sWf[(m0 + 1) * 8 + g];
        const float w8 = sWf[(m0 + 8) * 8 + g], w9 = sWf[(m0 + 9) * 8 + g];
        bhi0[kt] = pack_hi(w0, w1);
        blo0[kt] = pack_rn(w0 - trunc_bf(w0), w1 - trunc_bf(w1));
        bhi1[kt] = pack_hi(w8, w9);
        blo1[kt] = pack_rn(w8 - trunc_bf(w8), w9 - trunc_bf(w9));
    }

    // ---- this thread's two bins (fragment rows g and g+8) ----
    const int base_bin = blockIdx.x * 64 + wid * 16;
    const float yA = 2.0f * tanf(PI_F / (float)Lk * (float)(base_bin + g));
    const float yB = 2.0f * tanf(PI_F / (float)Lk * (float)(base_bin + g + 8));
    const float y2A = yA * yA, y2B = yB * yB;

    float D1[4] = {0, 0, 0, 0}, D2[4] = {0, 0, 0, 0};

#pragma unroll
    for (int kt = 0; kt < 4; kt++) {
        const int m0 = 16 * kt + 2 * tig;
        float p1A[4], p2A[4], p1B[4], p2B[4];
        const int mm[4] = { m0, m0 + 1, m0 + 8, m0 + 9 };
#pragma unroll
        for (int e = 0; e < 4; e++) {
            const float4 c = sC[mm[e]];
            const float uA = c.x - y2A;
            const float qA = frcp(fmaf(uA, uA, c.z * y2A));
            p1A[e] = uA * qA;  p2A[e] = c.y * qA;
            const float uB = c.x - y2B;
            const float qB = frcp(fmaf(uB, uB, c.z * y2B));
            p1B[e] = uB * qB;  p2B[e] = c.y * qB;
        }
        // A fragments: a0 = (rowA, k m0/m0+1), a1 = (rowB, same), a2/a3 = +8 cols
        uint32_t ah[4], al[4];
        ah[0] = pack_hi(p1A[0], p1A[1]);
        ah[1] = pack_hi(p1B[0], p1B[1]);
        ah[2] = pack_hi(p1A[2], p1A[3]);
        ah[3] = pack_hi(p1B[2], p1B[3]);
        al[0] = pack_rn(p1A[0] - trunc_bf(p1A[0]), p1A[1] - trunc_bf(p1A[1]));
        al[1] = pack_rn(p1B[0] - trunc_bf(p1B[0]), p1B[1] - trunc_bf(p1B[1]));
        al[2] = pack_rn(p1A[2] - trunc_bf(p1A[2]), p1A[3] - trunc_bf(p1A[3]));
        al[3] = pack_rn(p1B[2] - trunc_bf(p1B[2]), p1B[3] - trunc_bf(p1B[3]));
        mma_bf16(D1, ah, bhi0[kt], bhi1[kt]);
        mma_bf16(D1, ah, blo0[kt], blo1[kt]);
        mma_bf16(D1, al, bhi0[kt], bhi1[kt]);

        ah[0] = pack_hi(p2A[0], p2A[1]);
        ah[1] = pack_hi(p2B[0], p2B[1]);
        ah[2] = pack_hi(p2A[2], p2A[3]);
        ah[3] = pack_hi(p2B[2], p2B[3]);
        al[0] = pack_rn(p2A[0] - trunc_bf(p2A[0]), p2A[1] - trunc_bf(p2A[1]));
        al[1] = pack_rn(p2B[0] - trunc_bf(p2B[0]), p2B[1] - trunc_bf(p2B[1]));
        al[2] = pack_rn(p2A[2] - trunc_bf(p2A[2]), p2A[3] - trunc_bf(p2A[3]));
        al[3] = pack_rn(p2B[2] - trunc_bf(p2B[2]), p2B[3] - trunc_bf(p2B[3]));
        mma_bf16(D2, ah, bhi0[kt], bhi1[kt]);
        mma_bf16(D2, ah, blo0[kt], blo1[kt]);
        mma_bf16(D2, al, bhi0[kt], bhi1[kt]);
    }

    // ---- transpose D fragments so one lane owns one bin ----
    // D layout: c0=(row g, col 2tig), c1=(g, 2tig+1), c2=(g+8, 2tig), c3=(g+8, 2tig+1)
    sEx[wid][g][2 * tig]         = D1[0];
    sEx[wid][g][2 * tig + 1]     = D1[1];
    sEx[wid][g + 8][2 * tig]     = D1[2];
    sEx[wid][g + 8][2 * tig + 1] = D1[3];
    sEx[wid][g][8 + 2 * tig]         = D2[0];
    sEx[wid][g][8 + 2 * tig + 1]     = D2[1];
    sEx[wid][g + 8][8 + 2 * tig]     = D2[2];
    sEx[wid][g + 8][8 + 2 * tig + 1] = D2[3];
    __syncwarp();

    if (lane < 16) {
        const int j = base_bin + lane;
        const float y  = 2.0f * tanf(PI_F / (float)Lk * (float)j);
        const float y2 = y * y;
        const float* v = sEx[wid][lane];
        float rr[4], ri[4];
#pragma unroll
        for (int k = 0; k < 4; k++) {
            rr[k] = -fmaf(y2, v[8 + 2 * k], v[2 * k + 1]);
            ri[k] = y * (v[2 * k] - v[8 + 2 * k + 1]);
        }
        const float qr = 1.0f + rr[3], qi = ri[3];
        const float qn = frcp(fmaf(qr, qr, qi * qi));
        const float tr = rr[1] * rr[2] - ri[1] * ri[2];
        const float ti = rr[1] * ri[2] + ri[1] * rr[2];
        const float kr = rr[0] - (tr * qr + ti * qi) * qn;
        const float ki = ri[0] - (ti * qr - tr * qi) * qn;
        const float hh = 0.5f * y;
        g_kf[h * LHP + j] = make_float2(fmaf(-ki, hh, kr), fmaf(kr, hh, ki));
    }

    // Nyquist bin: analytic limit = sum Re(dt*B*C), real
    if (blockIdx.x == 0 && tid == 0) {
        const float dt = expf(log_dt[h]);
        float acc = 0.0f;
        for (int m = 0; m < NH; m++) {
            const int base = (h * NH + m) * 2;
            acc += B_ri[base] * C_ri[base] - B_ri[base + 1] * C_ri[base + 1];
        }
        g_kf[h * LHP + 1024] = make_float2(dt * acc, 0.0f);
    }
}

// ---------------------------------------------------------------------------
// K2: per-head inverse complex DFT (unchanged from R5). Stage 0 radix-2 fused
// with Hermitian load, then 5 radix-4 Stockham stages. 512 threads.
// ---------------------------------------------------------------------------
__global__ void __launch_bounds__(512) k_ifft(float* __restrict__ out)
{
    __shared__ float2 bufA[Lk];
    __shared__ float2 bufB[Lk];

    const int h = blockIdx.x;
    const int tid = threadIdx.x;
    const float2* __restrict__ kf = g_kf + h * LHP;

#pragma unroll
    for (int u = tid; u < Lk / 2; u += 512) {
        const float2 a = kf[u];
        float2 b;
        if (u == 0) b = kf[1024];
        else { const float2 t = kf[1024 - u]; b = make_float2(t.x, -t.y); }
        float s, cc;
        __sincosf(TWO_PI / (float)Lk * (float)u, &s, &cc);
        const float ax = a.x - b.x, ay = a.y - b.y;
        reinterpret_cast<float4*>(bufA)[u] =
            make_float4(a.x + b.x, a.y + b.y, ax * cc - ay * s, ax * s + ay * cc);
    }
    __syncthreads();

    float2* cur = bufA;
    float2* nxt = bufB;
#pragma unroll
    for (int s = 1; s <= 9; s += 2) {
        const float step = TWO_PI * (float)(1 << s) / (float)Lk;
        {
            const int g = tid;
            const int p  = g >> s;
            const int lo = g & ((1 << s) - 1);
            const int u1 = (p << s) | lo;
            const int u2 = u1 + Lk / 4;
            const float2 x0 = cur[u1], x2 = cur[u1 + Lk / 2];
            const float2 x1 = cur[u2], x3 = cur[u2 + Lk / 2];
            float s1, c1;
            __sincosf(step * (float)p, &s1, &c1);
            const float2 A0 = make_float2(x0.x + x2.x, x0.y + x2.y);
            const float dx = x0.x - x2.x, dy = x0.y - x2.y;
            const float2 A1 = make_float2(dx * c1 - dy * s1, dx * s1 + dy * c1);
            const float2 B0 = make_float2(x1.x + x3.x, x1.y + x3.y);
            const float ex = x1.x - x3.x, ey = x1.y - x3.y;
            const float tr = ex * c1 - ey * s1, ti = ex * s1 + ey * c1;
            const float2 B1 = make_float2(-ti, tr);
            const float c3 = c1 * c1 - s1 * s1, s3 = 2.0f * c1 * s1;
            const int O = (p << (s + 2)) | lo;
            const int q = 1 << s;
            nxt[O] = make_float2(A0.x + B0.x, A0.y + B0.y);
            const float fx = A0.x - B0.x, fy = A0.y - B0.y;
            nxt[O + 2 * q] = make_float2(fx * c3 - fy * s3, fx * s3 + fy * c3);
            nxt[O + q] = make_float2(A1.x + B1.x, A1.y + B1.y);
            const float gx = A1.x - B1.x, gy = A1.y - B1.y;
            nxt[O + 3 * q] = make_float2(gx * c3 - gy * s3, gx * s3 + gy * c3);
        }
        __syncthreads();
        float2* t = cur; cur = nxt; nxt = t;
    }

    const float inv = 1.0f / (float)Lk;
    float* o = out + h * Lk;
#pragma unroll
    for (int t = tid; t < Lk; t += 512)
        o[t] = cur[t].x * inv;
}

extern "C" void kernel_launch(void* const* d_in, const int* in_sizes, int n_in,
                              void* d_out, int out_size) {
    // metadata order: w_ri, P_ri, B_ri, C_ri, log_dt, L (L fixed at 2048)
    k_spectrum<<<dim3(16, Hn), 128>>>(
        (const float*)d_in[0],
        (const float*)d_in[1],
        (const float*)d_in[2],
        (const float*)d_in[3],
        (const float*)d_in[4]);
    k_ifft<<<Hn, 512>>>((float*)d_out);
}

// round 9
// speedup vs baseline: 1.5298x; 1.0202x over previous
#include <cuda_runtime.h>
#include <math.h>
#include <cstdint>

namespace {
constexpr int Hn  = 256;   // heads
constexpr int NH  = 64;    // complex modes per head
constexpr int Lk  = 2048;  // kernel length
constexpr int LHP = 1026;  // padded float2 stride per head
constexpr float TWO_PI = 6.28318530717958647692f;
constexpr float PI_F   = 3.14159265358979323846f;
}

// Inter-kernel scratch: spectrum k_f (2.1 MB, L2-resident)
__device__ float2 g_kf[Hn * LHP];

__device__ __forceinline__ float frcp(float x) {
    float r; asm("rcp.approx.f32 %0, %1;" : "=f"(r) : "f"(x)); return r;
}
// tf32 hi part: keep bits [31:13] (sign+exp+10 mantissa). Exact, ALU-pipe op.
__device__ __forceinline__ uint32_t tf32_hi_bits(float x) {
    return __float_as_uint(x) & 0xFFFFE000u;
}
// D[16x8] += A[16x8,row] * B[8x8,col]   (tf32 in regs as fp32 bits, f32 acc)
__device__ __forceinline__ void mma_tf32(float* d, const uint32_t* a,
                                         uint32_t b0, uint32_t b1) {
    asm volatile(
        "mma.sync.aligned.m16n8k8.row.col.f32.tf32.tf32.f32 "
        "{%0,%1,%2,%3}, {%4,%5,%6,%7}, {%8,%9}, {%0,%1,%2,%3};"
        : "+f"(d[0]), "+f"(d[1]), "+f"(d[2]), "+f"(d[3])
        : "r"(a[0]), "r"(a[1]), "r"(a[2]), "r"(a[3]), "r"(b0), "r"(b1));
}

// ---------------------------------------------------------------------------
// K1: spectrum via tf32-split warp MMA.
//   z = i*y, y = 2*tan(pi*j/L); per mode: u = m2 - y^2, d = u^2 + csq*y^2,
//   q = 1/d, P1 = u*q, P2' = cs*q   (m2=|w|^2, cs=2Re(w), csq=cs^2).
//   D1[bin,r] = sum_n P1*W[n,r], D2[bin,r] = sum_n P2'*W[n,r],
//   W cols r: {a0,b0,a1,b1,a2,b2,a3,b3}; a_k = 2Re(v_k), b_k = 2Re(v_k*conj(w)).
//   Re r_k = -(D1[2k+1] + y^2*D2[2k]),  Im r_k = y*(D1[2k] - D2[2k+1])
//   k_f = (r0 - r1*r2/(1+r3)) * (1 + i*y/2).  Nyquist analytic (real).
// grid (16, 256) x 128 thr; warp = 16-bin tile, block = 64 bins of head h.
// tf32 split: hi = mask13(x) exact; lo = x - hi exact fp32 (HW truncates lo
// to tf32 internally, residual ~2^-22). Products hh + hl + lh (lolo dropped).
// ---------------------------------------------------------------------------
__global__ void __launch_bounds__(128) k_spectrum(
    const float* __restrict__ w_ri,
    const float* __restrict__ P_ri,
    const float* __restrict__ B_ri,
    const float* __restrict__ C_ri,
    const float* __restrict__ log_dt)
{
    __shared__ float4 sC[NH];         // {m2, cs, csq, 0}
    __shared__ float  sWf[NH * 8];    // W[mode][r], fp32
    __shared__ float  sY[64], sY2[64];// per-bin y, y^2
    __shared__ float  sEx[4][16][16]; // per-warp transpose for epilogue

    const int h    = blockIdx.y;
    const int tid  = threadIdx.x;
    const int wid  = tid >> 5;
    const int lane = tid & 31;
    const int g    = lane >> 2;       // fragment group (row / B col)
    const int tig  = lane & 3;

    // ---- per-head constants + W ----
    if (tid < NH) {
        const int m = tid;
        const float dt = expf(log_dt[h]);
        const int base = (h * NH + m) * 2;
        const float wx = w_ri[base] * dt, wy = w_ri[base + 1] * dt;
        const float pr = P_ri[base], pi = P_ri[base + 1];
        const float br = B_ri[base], bi = B_ri[base + 1];
        const float cr = C_ri[base], ci = C_ri[base + 1];
        const float v00r = dt * (br * cr - bi * ci), v00i = dt * (br * ci + bi * cr);
        const float v01r = dt * (br * pr + bi * pi), v01i = dt * (bi * pr - br * pi);
        const float v10r = dt * (pr * cr - pi * ci), v10i = dt * (pr * ci + pi * cr);
        const float v11r = dt * (pr * pr + pi * pi);
        const float cs = 2.0f * wx;
        sC[m] = make_float4(wx * wx + wy * wy, cs, cs * cs, 0.0f);
        sWf[m * 8 + 0] = 2.0f * v00r;
        sWf[m * 8 + 1] = 2.0f * (v00r * wx + v00i * wy);
        sWf[m * 8 + 2] = 2.0f * v01r;
        sWf[m * 8 + 3] = 2.0f * (v01r * wx + v01i * wy);
        sWf[m * 8 + 4] = 2.0f * v10r;
        sWf[m * 8 + 5] = 2.0f * (v10r * wx + v10i * wy);
        sWf[m * 8 + 6] = 2.0f * v11r;
        sWf[m * 8 + 7] = 2.0f * v11r * wx;
        // per-bin y (64 bins per block): accurate tanf, once per bin
        const int j = blockIdx.x * 64 + m;
        const float y = 2.0f * tanf(PI_F / (float)Lk * (float)j);
        sY[m] = y;
        sY2[m] = y * y;
    }
    __syncthreads();

    // ---- B fragments (W hi/lo), 8 k-tiles of 8 modes ----
    uint32_t bh0[8], bh1[8], bl0[8], bl1[8];
#pragma unroll
    for (int kt = 0; kt < 8; kt++) {
        const float w0 = sWf[(8 * kt + tig) * 8 + g];
        const float w4 = sWf[(8 * kt + tig + 4) * 8 + g];
        bh0[kt] = tf32_hi_bits(w0);
        bl0[kt] = __float_as_uint(w0 - __uint_as_float(bh0[kt]));
        bh1[kt] = tf32_hi_bits(w4);
        bl1[kt] = __float_as_uint(w4 - __uint_as_float(bh1[kt]));
    }

    // ---- this warp's bins: rows g and g+8 of tile ----
    const int base_loc = wid * 16;                 // local bin of row 0
    const float yA2 = sY2[base_loc + g];
    const float yB2 = sY2[base_loc + g + 8];

    float D1[4] = {0, 0, 0, 0}, D2[4] = {0, 0, 0, 0};

#pragma unroll
    for (int kt = 0; kt < 8; kt++) {
        // pairs: modes m0 = 8kt+tig, m1 = 8kt+tig+4; bins A (row g), B (row g+8)
        const float4 c0 = sC[8 * kt + tig];
        const float4 c1 = sC[8 * kt + tig + 4];

        const float u00 = c0.x - yA2;                            // (A, m0)
        const float q00 = frcp(fmaf(u00, u00, c0.z * yA2));
        const float u01 = c0.x - yB2;                            // (B, m0)
        const float q01 = frcp(fmaf(u01, u01, c0.z * yB2));
        const float u10 = c1.x - yA2;                            // (A, m1)
        const float q10 = frcp(fmaf(u10, u10, c1.z * yA2));
        const float u11 = c1.x - yB2;                            // (B, m1)
        const float q11 = frcp(fmaf(u11, u11, c1.z * yB2));

        // P1 = u*q : A-fragment a0=(g,tig) a1=(g+8,tig) a2=(g,tig+4) a3=(g+8,tig+4)
        float p[4];
        p[0] = u00 * q00; p[1] = u01 * q01; p[2] = u10 * q10; p[3] = u11 * q11;
        uint32_t ah[4], al[4];
#pragma unroll
        for (int e = 0; e < 4; e++) {
            ah[e] = tf32_hi_bits(p[e]);
            al[e] = __float_as_uint(p[e] - __uint_as_float(ah[e]));
        }
        mma_tf32(D1, ah, bh0[kt], bh1[kt]);
        mma_tf32(D1, ah, bl0[kt], bl1[kt]);
        mma_tf32(D1, al, bh0[kt], bh1[kt]);

        // P2' = cs*q
        p[0] = c0.y * q00; p[1] = c0.y * q01; p[2] = c1.y * q10; p[3] = c1.y * q11;
#pragma unroll
        for (int e = 0; e < 4; e++) {
            ah[e] = tf32_hi_bits(p[e]);
            al[e] = __float_as_uint(p[e] - __uint_as_float(ah[e]));
        }
        mma_tf32(D2, ah, bh0[kt], bh1[kt]);
        mma_tf32(D2, ah, bl0[kt], bl1[kt]);
        mma_tf32(D2, al, bh0[kt], bh1[kt]);
    }

    // ---- transpose D fragments so one lane owns one bin ----
    sEx[wid][g][2 * tig]         = D1[0];
    sEx[wid][g][2 * tig + 1]     = D1[1];
    sEx[wid][g + 8][2 * tig]     = D1[2];
    sEx[wid][g + 8][2 * tig + 1] = D1[3];
    sEx[wid][g][8 + 2 * tig]         = D2[0];
    sEx[wid][g][8 + 2 * tig + 1]     = D2[1];
    sEx[wid][g + 8][8 + 2 * tig]     = D2[2];
    sEx[wid][g + 8][8 + 2 * tig + 1] = D2[3];
    __syncwarp();

    if (lane < 16) {
        const int loc = base_loc + lane;
        const int j = blockIdx.x * 64 + loc;
        const float y  = sY[loc];
        const float y2 = sY2[loc];
        const float* v = sEx[wid][lane];
        float rr[4], ri[4];
#pragma unroll
        for (int k = 0; k < 4; k++) {
            rr[k] = -fmaf(y2, v[8 + 2 * k], v[2 * k + 1]);
            ri[k] = y * (v[2 * k] - v[8 + 2 * k + 1]);
        }
        const float qr = 1.0f + rr[3], qi = ri[3];
        const float qn = frcp(fmaf(qr, qr, qi * qi));
        const float tr = rr[1] * rr[2] - ri[1] * ri[2];
        const float ti = rr[1] * ri[2] + ri[1] * rr[2];
        const float kr = rr[0] - (tr * qr + ti * qi) * qn;
        const float ki = ri[0] - (ti * qr - tr * qi) * qn;
        const float hh = 0.5f * y;
        g_kf[h * LHP + j] = make_float2(fmaf(-ki, hh, kr), fmaf(kr, hh, ki));
    }

    // Nyquist bin: analytic limit = sum Re(dt*B*C), real
    if (blockIdx.x == 0 && tid == 0) {
        const float dt = expf(log_dt[h]);
        float acc = 0.0f;
        for (int m = 0; m < NH; m++) {
            const int base = (h * NH + m) * 2;
            acc += B_ri[base] * C_ri[base] - B_ri[base + 1] * C_ri[base + 1];
        }
        g_kf[h * LHP + 1024] = make_float2(dt * acc, 0.0f);
    }
}

// ---------------------------------------------------------------------------
// K2: per-head inverse complex DFT. Stage 0 radix-2 fused with Hermitian
// load, then 5 radix-4 Stockham stages. 512 threads.
// ---------------------------------------------------------------------------
__global__ void __launch_bounds__(512) k_ifft(float* __restrict__ out)
{
    __shared__ float2 bufA[Lk];
    __shared__ float2 bufB[Lk];

    const int h = blockIdx.x;
    const int tid = threadIdx.x;
    const float2* __restrict__ kf = g_kf + h * LHP;

#pragma unroll
    for (int u = tid; u < Lk / 2; u += 512) {
        const float2 a = kf[u];
        float2 b;
        if (u == 0) b = kf[1024];
        else { const float2 t = kf[1024 - u]; b = make_float2(t.x, -t.y); }
        float s, cc;
        __sincosf(TWO_PI / (float)Lk * (float)u, &s, &cc);
        const float ax = a.x - b.x, ay = a.y - b.y;
        reinterpret_cast<float4*>(bufA)[u] =
            make_float4(a.x + b.x, a.y + b.y, ax * cc - ay * s, ax * s + ay * cc);
    }
    __syncthreads();

    float2* cur = bufA;
    float2* nxt = bufB;
#pragma unroll
    for (int s = 1; s <= 9; s += 2) {
        const float step = TWO_PI * (float)(1 << s) / (float)Lk;
        {
            const int g = tid;
            const int p  = g >> s;
            const int lo = g & ((1 << s) - 1);
            const int u1 = (p << s) | lo;
            const int u2 = u1 + Lk / 4;
            const float2 x0 = cur[u1], x2 = cur[u1 + Lk / 2];
            const float2 x1 = cur[u2], x3 = cur[u2 + Lk / 2];
            float s1, c1;
            __sincosf(step * (float)p, &s1, &c1);
            const float2 A0 = make_float2(x0.x + x2.x, x0.y + x2.y);
            const float dx = x0.x - x2.x, dy = x0.y - x2.y;
            const float2 A1 = make_float2(dx * c1 - dy * s1, dx * s1 + dy * c1);
            const float2 B0 = make_float2(x1.x + x3.x, x1.y + x3.y);
            const float ex = x1.x - x3.x, ey = x1.y - x3.y;
            const float tr = ex * c1 - ey * s1, ti = ex * s1 + ey * c1;
            const float2 B1 = make_float2(-ti, tr);
            const float c3 = c1 * c1 - s1 * s1, s3 = 2.0f * c1 * s1;
            const int O = (p << (s + 2)) | lo;
            const int q = 1 << s;
            nxt[O] = make_float2(A0.x + B0.x, A0.y + B0.y);
            const float fx = A0.x - B0.x, fy = A0.y - B0.y;
            nxt[O + 2 * q] = make_float2(fx * c3 - fy * s3, fx * s3 + fy * c3);
            nxt[O + q] = make_float2(A1.x + B1.x, A1.y + B1.y);
            const float gx = A1.x - B1.x, gy = A1.y - B1.y;
            nxt[O + 3 * q] = make_float2(gx * c3 - gy * s3, gx * s3 + gy * c3);
        }
        __syncthreads();
        float2* t = cur; cur = nxt; nxt = t;
    }

    const float inv = 1.0f / (float)Lk;
    float* o = out + h * Lk;
#pragma unroll
    for (int t = tid; t < Lk; t += 512)
        o[t] = cur[t].x * inv;
}

extern "C" void kernel_launch(void* const* d_in, const int* in_sizes, int n_in,
                              void* d_out, int out_size) {
    // metadata order: w_ri, P_ri, B_ri, C_ri, log_dt, L (L fixed at 2048)
    k_spectrum<<<dim3(16, Hn), 128>>>(
        (const float*)d_in[0],
        (const float*)d_in[1],
        (const float*)d_in[2],
        (const float*)d_in[3],
        (const float*)d_in[4]);
    k_ifft<<<Hn, 512>>>((float*)d_out);
}